// round 15
// baseline (speedup 1.0000x reference)
#include <cuda_runtime.h>
#include <cuda_bf16.h>
#include <cstdint>
#include <cstddef>
#include <math.h>

// Problem constants (B=128, N=511, M=256, R=64, IN=512)
#define BATCH  128
#define NNODES 511
#define MDIM   256
#define RDIM   64
#define INDIM  512

// ---------------- persistent device scratch (no allocation) ----------------
__device__ __align__(16) float g_c_buf[(size_t)NNODES * BATCH * MDIM];
__device__ __align__(16) float g_c1[(size_t)128 * BATCH * MDIM];

// bf16 split activations
__device__ __align__(16) __nv_bfloat16 g_wte_hi[(size_t)BATCH * NNODES * INDIM];
__device__ __align__(16) __nv_bfloat16 g_wte_lo[(size_t)BATCH * NNODES * INDIM];
__device__ __align__(16) __nv_bfloat16 g_relb_hi[(size_t)BATCH * NNODES * RDIM];
__device__ __align__(16) __nv_bfloat16 g_relb_lo[(size_t)BATCH * NNODES * RDIM];
__device__ __align__(16) __nv_bfloat16 g_hb_hi[(size_t)NNODES * BATCH * MDIM];
__device__ __align__(16) __nv_bfloat16 g_hb_lo[(size_t)NNODES * BATCH * MDIM];
__device__ __align__(16) __nv_bfloat16 g_h1b_hi[(size_t)128 * BATCH * MDIM];
__device__ __align__(16) __nv_bfloat16 g_h1b_lo[(size_t)128 * BATCH * MDIM];
__device__ __align__(16) __nv_bfloat16 g_htb_hi[(size_t)128 * BATCH * MDIM];
__device__ __align__(16) __nv_bfloat16 g_htb_lo[(size_t)128 * BATCH * MDIM];

// bf16 split weights (transposed [N][K])
__device__ __align__(16) __nv_bfloat16 g_wg_hi[1024 * 512];    // x-proj: i,u,o,fx
__device__ __align__(16) __nv_bfloat16 g_wg_lo[1024 * 512];
__device__ __align__(16) __nv_bfloat16 g_wsr_hi[1024 * 64];    // rel-proj: seq i,f,g,o
__device__ __align__(16) __nv_bfloat16 g_wsr_lo[1024 * 64];
__device__ __align__(16) __nv_bfloat16 g_wc1_hi[768 * 256];    // cell1 h: i,g,o
__device__ __align__(16) __nv_bfloat16 g_wc1_lo[768 * 256];
__device__ __align__(16) __nv_bfloat16 g_wc2_hi[1024 * 512];   // cell2 h,h1: i,f,g,o
__device__ __align__(16) __nv_bfloat16 g_wc2_lo[1024 * 512];
__device__ __align__(16) __nv_bfloat16 g_wgh_hi[768 * 256];    // gates h: i,u,o
__device__ __align__(16) __nv_bfloat16 g_wgh_lo[768 * 256];
__device__ __align__(16) __nv_bfloat16 g_wfh_hi[256 * 256];
__device__ __align__(16) __nv_bfloat16 g_wfh_lo[256 * 256];

// projection / pre-activation scratch
__device__ __align__(16) float g_xproj[(size_t)65408 * 1024];   // row = b*511+node
__device__ __align__(16) float g_relproj[(size_t)65408 * 1024];
__device__ __align__(16) float g_pre1[(size_t)16384 * 768];
__device__ __align__(16) float g_pre2[(size_t)16384 * 1024];
__device__ __align__(16) float g_preg[(size_t)16384 * 768];
__device__ __align__(16) float g_pref[(size_t)32768 * 256];

__device__ __forceinline__ float sigf(float x) { return 1.0f / (1.0f + expf(-x)); }

__device__ __forceinline__ void split2(float x, unsigned short& h, unsigned short& l) {
    __nv_bfloat16 bh = __float2bfloat16(x);
    h = __bfloat16_as_ushort(bh);
    l = __bfloat16_as_ushort(__float2bfloat16(x - __bfloat162float(bh)));
}

// ---- mma.sync helpers ----
__device__ __forceinline__ uint32_t smem_u32(const void* p) {
    uint32_t a;
    asm("{ .reg .u64 t; cvta.to.shared.u64 t, %1; cvt.u32.u64 %0, t; }" : "=r"(a) : "l"(p));
    return a;
}
__device__ __forceinline__ void ldm4(uint32_t* r, uint32_t addr) {
    asm volatile("ldmatrix.sync.aligned.m8n8.x4.shared.b16 {%0,%1,%2,%3}, [%4];"
        : "=r"(r[0]), "=r"(r[1]), "=r"(r[2]), "=r"(r[3]) : "r"(addr));
}
__device__ __forceinline__ void mma_bf16(float* c, const uint32_t* a,
                                         uint32_t b0, uint32_t b1) {
    asm volatile(
        "mma.sync.aligned.m16n8k16.row.col.f32.bf16.bf16.f32 "
        "{%0,%1,%2,%3}, {%4,%5,%6,%7}, {%8,%9}, {%0,%1,%2,%3};"
        : "+f"(c[0]), "+f"(c[1]), "+f"(c[2]), "+f"(c[3])
        : "r"(a[0]), "r"(a[1]), "r"(a[2]), "r"(a[3]), "r"(b0), "r"(b1));
}
#define CPA16(s, g) asm volatile("cp.async.cg.shared.global [%0], [%1], 16;" :: "r"(s), "l"(g))
#define CPC() asm volatile("cp.async.commit_group;" ::: "memory")
#define CPW(n) asm volatile("cp.async.wait_group %0;" :: "n"(n) : "memory")

// ======================= conversion kernels =======================
__global__ void __launch_bounds__(256)
k_conv_wte(const float* __restrict__ src)
{
    size_t i = ((size_t)blockIdx.x * 256 + threadIdx.x) * 4;
    float4 v = *reinterpret_cast<const float4*>(src + i);
    ushort4 H, L;
#pragma unroll
    for (int q = 0; q < 4; q++) split2((&v.x)[q], (&H.x)[q], (&L.x)[q]);
    *reinterpret_cast<ushort4*>(g_wte_hi + i) = H;
    *reinterpret_cast<ushort4*>(g_wte_lo + i) = L;
}

__global__ void __launch_bounds__(256)
k_conv_rel(const float* __restrict__ src)
{
    size_t i = ((size_t)blockIdx.x * 256 + threadIdx.x) * 4;
    float4 v = *reinterpret_cast<const float4*>(src + i);
    ushort4 H, L;
#pragma unroll
    for (int q = 0; q < 4; q++) split2((&v.x)[q], (&H.x)[q], (&L.x)[q]);
    *reinterpret_cast<ushort4*>(g_relb_hi + i) = H;
    *reinterpret_cast<ushort4*>(g_relb_lo + i) = L;
}

__global__ void __launch_bounds__(256)
k_conv_wg(const float* __restrict__ Wix, const float* __restrict__ Wux,
          const float* __restrict__ Wox, const float* __restrict__ Wfx)
{
    int idx = blockIdx.x * 256 + threadIdx.x;     // [1024][512]
    int n = idx >> 9, k = idx & 511;
    int m = n & 255, gate = n >> 8;
    const float* W = (gate == 0) ? Wix : (gate == 1) ? Wux : (gate == 2) ? Wox : Wfx;
    float x = W[(size_t)k * 256 + m];
    unsigned short h, l;
    split2(x, h, l);
    g_wg_hi[idx] = __ushort_as_bfloat16(h);
    g_wg_lo[idx] = __ushort_as_bfloat16(l);
}

__global__ void __launch_bounds__(256)
k_conv_wsr(const float* __restrict__ Wsih)
{
    int idx = blockIdx.x * 256 + threadIdx.x;     // [1024][64]
    int n = idx >> 6, k = idx & 63;
    float x = Wsih[(size_t)(256 + k) * 1024 + n];
    unsigned short h, l;
    split2(x, h, l);
    g_wsr_hi[idx] = __ushort_as_bfloat16(h);
    g_wsr_lo[idx] = __ushort_as_bfloat16(l);
}

__global__ void __launch_bounds__(256)
k_conv_wc1(const float* __restrict__ Wsih)
{
    int idx = blockIdx.x * 256 + threadIdx.x;     // [768][256]: i,g,o
    int n = idx >> 8, k = idx & 255;
    int m = n & 255, gsel = n >> 8;
    int cbase = (gsel == 0) ? 0 : (gsel == 1 ? 512 : 768);
    float x = Wsih[(size_t)k * 1024 + cbase + m];
    unsigned short h, l;
    split2(x, h, l);
    g_wc1_hi[idx] = __ushort_as_bfloat16(h);
    g_wc1_lo[idx] = __ushort_as_bfloat16(l);
}

__global__ void __launch_bounds__(256)
k_conv_wc2(const float* __restrict__ Wsih, const float* __restrict__ Wshh)
{
    int idx = blockIdx.x * 256 + threadIdx.x;     // [1024][512]: i,f,g,o ; K = h(256)+h1(256)
    int n = idx >> 9, k = idx & 511;
    int m = n & 255, cbase = (n >> 8) * 256;
    float x = (k < 256) ? Wsih[(size_t)k * 1024 + cbase + m]
                        : Wshh[(size_t)(k - 256) * 1024 + cbase + m];
    unsigned short h, l;
    split2(x, h, l);
    g_wc2_hi[idx] = __ushort_as_bfloat16(h);
    g_wc2_lo[idx] = __ushort_as_bfloat16(l);
}

__global__ void __launch_bounds__(256)
k_conv_wgh(const float* __restrict__ Wih, const float* __restrict__ Wuh,
           const float* __restrict__ Woh)
{
    int idx = blockIdx.x * 256 + threadIdx.x;     // [768][256]: i,u,o
    int n = idx >> 8, k = idx & 255;
    int m = n & 255, gate = n >> 8;
    const float* W = (gate == 0) ? Wih : (gate == 1) ? Wuh : Woh;
    float x = W[(size_t)k * 256 + m];
    unsigned short h, l;
    split2(x, h, l);
    g_wgh_hi[idx] = __ushort_as_bfloat16(h);
    g_wgh_lo[idx] = __ushort_as_bfloat16(l);
}

__global__ void __launch_bounds__(256)
k_conv_wfh(const float* __restrict__ Wfh)
{
    int idx = blockIdx.x * 256 + threadIdx.x;     // [256][256]
    int n = idx >> 8, k = idx & 255;
    float x = Wfh[(size_t)k * 256 + n];
    unsigned short h, l;
    split2(x, h, l);
    g_wfh_hi[idx] = __ushort_as_bfloat16(h);
    g_wfh_lo[idx] = __ushort_as_bfloat16(l);
}

// ======================= generic bf16-split mma GEMM =======================
// Block 128 rows x 256 cols, 256 threads, 8 warps each m64 x n64.
// K in 64-chunks, 2-stage cp.async.
// MODE: 0=cell1(h,K256) 1=cell2(h|h1,K512) 2=gates-h(K256) 3=f(K256)
//       5=bigX(wte,K512) 6=bigR(rel,K64)
#define LPITCH 144
// stage layout (bytes): Ah@0 (128 rows), Al@18432, Bh@36864 (256 rows), Bl@73728
#define STG 110592

template<int MODE, int NC, int COLS, int KTOT>
__global__ void __launch_bounds__(256, 1)
k_mma(int nodeBase, int P)
{
    extern __shared__ char sm[];
    const int tid = threadIdx.x;
    const int rt = blockIdx.x, ny = blockIdx.y;
    const int lane = tid & 31, wid = tid >> 5;            // wid 0..7
    const int wm = (wid & 1) * 64, wn = (wid >> 1) * 64;  // m64 x n64 warp tiles
    const int r = tid >> 1, half = tid & 1;               // A staging
    const int rb2 = tid;                                  // B staging: one row/thread

    const __nv_bfloat16* WH;
    const __nv_bfloat16* WL;
    float* pre;
    if (MODE == 0)      { WH = g_wc1_hi; WL = g_wc1_lo; pre = g_pre1; }
    else if (MODE == 1) { WH = g_wc2_hi; WL = g_wc2_lo; pre = g_pre2; }
    else if (MODE == 2) { WH = g_wgh_hi; WL = g_wgh_lo; pre = g_preg; }
    else if (MODE == 3) { WH = g_wfh_hi; WL = g_wfh_lo; pre = g_pref; }
    else if (MODE == 5) { WH = g_wg_hi;  WL = g_wg_lo;  pre = g_xproj; }
    else                { WH = g_wsr_hi; WL = g_wsr_lo; pre = g_relproj; }

    const __nv_bfloat16 *pA0h = nullptr, *pA0l = nullptr;
    const __nv_bfloat16 *pA2h = nullptr, *pA2l = nullptr;
    if (MODE == 5) {
        size_t R = (size_t)rt * 128 + r;
        pA0h = g_wte_hi + R * 512;
        pA0l = g_wte_lo + R * 512;
    } else if (MODE == 6) {
        size_t R = (size_t)rt * 128 + r;
        pA0h = g_relb_hi + R * 64;
        pA0l = g_relb_lo + R * 64;
    } else if (MODE == 3) {
        int rt2 = (rt < P) ? rt : rt - P;
        int rl = rt2 * 128 + r;
        int node = nodeBase + (rl >> 7);
        int b = rl & 127;
        int ch = (rt < P) ? (2 * node + 1) : (2 * node + 2);
        pA0h = g_hb_hi + ((size_t)ch * BATCH + b) * 256;
        pA0l = g_hb_lo + ((size_t)ch * BATCH + b) * 256;
    } else {
        int rl = rt * 128 + r;
        int node = nodeBase + (rl >> 7);
        int b = rl & 127;
        if (MODE == 0) {
            int ch = 2 * node + 1;
            pA0h = g_hb_hi + ((size_t)ch * BATCH + b) * 256;
            pA0l = g_hb_lo + ((size_t)ch * BATCH + b) * 256;
        } else if (MODE == 1) {
            int ch = 2 * node + 2;
            pA0h = g_hb_hi + ((size_t)ch * BATCH + b) * 256;
            pA0l = g_hb_lo + ((size_t)ch * BATCH + b) * 256;
            pA2h = g_h1b_hi + (size_t)rl * 256;
            pA2l = g_h1b_lo + (size_t)rl * 256;
        } else {   // MODE 2
            pA0h = g_htb_hi + (size_t)rl * 256;
            pA0l = g_htb_lo + (size_t)rl * 256;
        }
    }
    const __nv_bfloat16* pBh = WH + (size_t)(ny * 256 + rb2) * KTOT;
    const __nv_bfloat16* pBl = WL + (size_t)(ny * 256 + rb2) * KTOT;

    const uint32_t sbase = smem_u32(sm);

    auto stage = [&](int c, int s) {
        uint32_t base = sbase + (uint32_t)s * STG;
        {   // A: 128 rows, 2 threads/row
            const __nv_bfloat16 *ah, *al;
            if (MODE == 1 && c >= 4) { ah = pA2h + (c - 4) * 64; al = pA2l + (c - 4) * 64; }
            else                     { ah = pA0h + c * 64;       al = pA0l + c * 64; }
            const char* gah = reinterpret_cast<const char*>(ah + half * 32);
            const char* gal = reinterpret_cast<const char*>(al + half * 32);
            uint32_t ab = base + (uint32_t)r * LPITCH + half * 64;
#pragma unroll
            for (int i = 0; i < 4; i++) {
                CPA16(ab + 0     + i * 16, gah + i * 16);
                CPA16(ab + 18432 + i * 16, gal + i * 16);
            }
        }
        {   // B: 256 rows, 1 thread/row
            const char* gbh = reinterpret_cast<const char*>(pBh + c * 64);
            const char* gbl = reinterpret_cast<const char*>(pBl + c * 64);
            uint32_t bb = base + 36864 + (uint32_t)rb2 * LPITCH;
#pragma unroll
            for (int i = 0; i < 8; i++) {
                CPA16(bb + 0     + i * 16, gbh + i * 16);
                CPA16(bb + 36864 + i * 16, gbl + i * 16);
            }
        }
        CPC();
    };

    float cacc[4][8][4];
#pragma unroll
    for (int mt = 0; mt < 4; mt++)
#pragma unroll
        for (int j = 0; j < 8; j++)
#pragma unroll
            for (int q = 0; q < 4; q++) cacc[mt][j][q] = 0.0f;

    stage(0, 0);
    for (int c = 0; c < NC; c++) {
        if (c + 1 < NC) { stage(c + 1, (c + 1) & 1); CPW(1); }
        else            { CPW(0); }
        __syncthreads();
        const uint32_t sb = sbase + (uint32_t)(c & 1) * STG;
        const uint32_t aH = sb + 0     + (uint32_t)(wm + (lane & 15)) * LPITCH + (lane >> 4) * 16;
        const uint32_t aL = sb + 18432 + (uint32_t)(wm + (lane & 15)) * LPITCH + (lane >> 4) * 16;
        const uint32_t bH = sb + 36864 + (uint32_t)(wn + (lane & 15)) * LPITCH + (lane >> 4) * 16;
        const uint32_t bL = sb + 73728 + (uint32_t)(wn + (lane & 15)) * LPITCH + (lane >> 4) * 16;
#pragma unroll
        for (int ks = 0; ks < 4; ks++) {
            const uint32_t kb = ks * 32;
            uint32_t bh[8][2], bl[8][2];
#pragma unroll
            for (int p = 0; p < 4; p++) {
                uint32_t t[4];
                ldm4(t, bH + (uint32_t)p * 16 * LPITCH + kb);
                bh[p * 2][0] = t[0]; bh[p * 2][1] = t[2];
                bh[p * 2 + 1][0] = t[1]; bh[p * 2 + 1][1] = t[3];
                ldm4(t, bL + (uint32_t)p * 16 * LPITCH + kb);
                bl[p * 2][0] = t[0]; bl[p * 2][1] = t[2];
                bl[p * 2 + 1][0] = t[1]; bl[p * 2 + 1][1] = t[3];
            }
#pragma unroll
            for (int mt = 0; mt < 4; mt++) {
                uint32_t ah[4], al[4];
                ldm4(ah, aH + (uint32_t)mt * 16 * LPITCH + kb);
                ldm4(al, aL + (uint32_t)mt * 16 * LPITCH + kb);
#pragma unroll
                for (int j = 0; j < 8; j++) {
                    mma_bf16(cacc[mt][j], ah, bh[j][0], bh[j][1]);
                    mma_bf16(cacc[mt][j], ah, bl[j][0], bl[j][1]);
                    mma_bf16(cacc[mt][j], al, bh[j][0], bh[j][1]);
                }
            }
        }
        __syncthreads();
    }

#pragma unroll
    for (int mt = 0; mt < 4; mt++) {
#pragma unroll
        for (int j = 0; j < 8; j++) {
            size_t row = (size_t)rt * 128 + wm + mt * 16 + (lane >> 2);
            int nn = ny * 256 + wn + j * 8 + (lane & 3) * 2;
            float* dst = pre + row * COLS + nn;
            *reinterpret_cast<float2*>(dst) = make_float2(cacc[mt][j][0], cacc[mt][j][1]);
            *reinterpret_cast<float2*>(dst + (size_t)8 * COLS) = make_float2(cacc[mt][j][2], cacc[mt][j][3]);
        }
    }
}

// ======================= combine kernels =======================
__global__ void __launch_bounds__(256)
k_comb_leaf(const float* __restrict__ bix, const float* __restrict__ bih,
            const float* __restrict__ bux, const float* __restrict__ buh,
            const float* __restrict__ boxb, const float* __restrict__ boh)
{
    int idx = blockIdx.x * 256 + threadIdx.x;
    int lin = idx * 4;
    int row = lin >> 8, m = lin & 255;
    int node = 255 + (row >> 7);
    int b = row & 127;
    const float* p = g_xproj + ((size_t)b * NNODES + node) * 1024;
    float4 vi = *reinterpret_cast<const float4*>(p + m);
    float4 vu = *reinterpret_cast<const float4*>(p + 256 + m);
    float4 vo = *reinterpret_cast<const float4*>(p + 512 + m);
    size_t base = ((size_t)node * BATCH + b) * MDIM + m;
    float4 cv;
    ushort4 hh, hl;
#pragma unroll
    for (int q = 0; q < 4; q++) {
        float iv = sigf((&vi.x)[q] + bix[m + q] + bih[m + q]);
        float uv = tanhf((&vu.x)[q] + bux[m + q] + buh[m + q]);
        float ov = sigf((&vo.x)[q] + boxb[m + q] + boh[m + q]);
        float c = iv * uv;
        (&cv.x)[q] = c;
        split2(ov * tanhf(c), (&hh.x)[q], (&hl.x)[q]);
    }
    *reinterpret_cast<float4*>(&g_c_buf[base]) = cv;
    *reinterpret_cast<ushort4*>(g_hb_hi + base) = hh;
    *reinterpret_cast<ushort4*>(g_hb_lo + base) = hl;
}

__global__ void __launch_bounds__(256)
k_comb_c1(const float* __restrict__ bsi, const float* __restrict__ bsh, int nodeBase)
{
    int idx = blockIdx.x * 256 + threadIdx.x;
    int lin = idx * 4;
    int row = lin >> 8, m = lin & 255;
    int node = nodeBase + (row >> 7);
    int b = row & 127;
    int ch = 2 * node + 1;
    const float* p = g_pre1 + (size_t)row * 768;
    const float* rp = g_relproj + ((size_t)b * NNODES + ch) * 1024;
    float4 vi = *reinterpret_cast<const float4*>(p + m);
    float4 vg = *reinterpret_cast<const float4*>(p + 256 + m);
    float4 vo = *reinterpret_cast<const float4*>(p + 512 + m);
    float4 ri = *reinterpret_cast<const float4*>(rp + m);
    float4 rg = *reinterpret_cast<const float4*>(rp + 512 + m);
    float4 ro = *reinterpret_cast<const float4*>(rp + 768 + m);
    size_t base = (size_t)row * MDIM + m;
    float4 cv;
    ushort4 hh, hl;
#pragma unroll
    for (int q = 0; q < 4; q++) {
        float iv = sigf((&vi.x)[q] + (&ri.x)[q] + bsi[m + q] + bsh[m + q]);
        float gv = tanhf((&vg.x)[q] + (&rg.x)[q] + bsi[512 + m + q] + bsh[512 + m + q]);
        float ov = sigf((&vo.x)[q] + (&ro.x)[q] + bsi[768 + m + q] + bsh[768 + m + q]);
        float c1 = iv * gv;
        (&cv.x)[q] = c1;
        split2(ov * tanhf(c1), (&hh.x)[q], (&hl.x)[q]);
    }
    *reinterpret_cast<float4*>(&g_c1[base]) = cv;
    *reinterpret_cast<ushort4*>(g_h1b_hi + base) = hh;
    *reinterpret_cast<ushort4*>(g_h1b_lo + base) = hl;
}

__global__ void __launch_bounds__(256)
k_comb_c2(const float* __restrict__ bsi, const float* __restrict__ bsh, int nodeBase)
{
    int idx = blockIdx.x * 256 + threadIdx.x;
    int lin = idx * 4;
    int row = lin >> 8, m = lin & 255;
    int node = nodeBase + (row >> 7);
    int b = row & 127;
    int ch = 2 * node + 2;
    const float* p = g_pre2 + (size_t)row * 1024;
    const float* rp = g_relproj + ((size_t)b * NNODES + ch) * 1024;
    float4 vi = *reinterpret_cast<const float4*>(p + m);
    float4 vf = *reinterpret_cast<const float4*>(p + 256 + m);
    float4 vg = *reinterpret_cast<const float4*>(p + 512 + m);
    float4 vo = *reinterpret_cast<const float4*>(p + 768 + m);
    float4 ri = *reinterpret_cast<const float4*>(rp + m);
    float4 rf = *reinterpret_cast<const float4*>(rp + 256 + m);
    float4 rg = *reinterpret_cast<const float4*>(rp + 512 + m);
    float4 ro = *reinterpret_cast<const float4*>(rp + 768 + m);
    size_t base = (size_t)row * MDIM + m;
    float4 c1v = *reinterpret_cast<const float4*>(&g_c1[base]);
    ushort4 hh, hl;
#pragma unroll
    for (int q = 0; q < 4; q++) {
        float iv = sigf((&vi.x)[q] + (&ri.x)[q] + bsi[m + q] + bsh[m + q]);
        float fv = sigf((&vf.x)[q] + (&rf.x)[q] + bsi[256 + m + q] + bsh[256 + m + q]);
        float gv = tanhf((&vg.x)[q] + (&rg.x)[q] + bsi[512 + m + q] + bsh[512 + m + q]);
        float ov = sigf((&vo.x)[q] + (&ro.x)[q] + bsi[768 + m + q] + bsh[768 + m + q]);
        float c2 = fv * (&c1v.x)[q] + iv * gv;
        split2(ov * tanhf(c2), (&hh.x)[q], (&hl.x)[q]);
    }
    *reinterpret_cast<ushort4*>(g_htb_hi + base) = hh;
    *reinterpret_cast<ushort4*>(g_htb_lo + base) = hl;
}

__global__ void __launch_bounds__(256)
k_comb_fin(const float* __restrict__ bix, const float* __restrict__ bih,
           const float* __restrict__ bux, const float* __restrict__ buh,
           const float* __restrict__ boxb, const float* __restrict__ boh,
           const float* __restrict__ bfx, const float* __restrict__ bfh,
           int nodeBase, int P, float* __restrict__ outp)
{
    int idx = blockIdx.x * 256 + threadIdx.x;
    int lin = idx * 4;
    int row = lin >> 8, m = lin & 255;
    int node = nodeBase + (row >> 7);
    int b = row & 127;
    const float* p = g_preg + (size_t)row * 768;
    const float* xp = g_xproj + ((size_t)b * NNODES + node) * 1024;
    float4 vi = *reinterpret_cast<const float4*>(p + m);
    float4 vu = *reinterpret_cast<const float4*>(p + 256 + m);
    float4 vo = *reinterpret_cast<const float4*>(p + 512 + m);
    float4 xi = *reinterpret_cast<const float4*>(xp + m);
    float4 xu = *reinterpret_cast<const float4*>(xp + 256 + m);
    float4 xo = *reinterpret_cast<const float4*>(xp + 512 + m);
    float4 xf = *reinterpret_cast<const float4*>(xp + 768 + m);
    float4 f0 = *reinterpret_cast<const float4*>(g_pref + (size_t)row * 256 + m);
    float4 f1 = *reinterpret_cast<const float4*>(g_pref + ((size_t)P * 128 + row) * 256 + m);
    size_t base  = ((size_t)node * BATCH + b) * MDIM + m;
    size_t base0 = ((size_t)(2 * node + 1) * BATCH + b) * MDIM + m;
    size_t base1 = ((size_t)(2 * node + 2) * BATCH + b) * MDIM + m;
    float4 cc0 = *reinterpret_cast<const float4*>(&g_c_buf[base0]);
    float4 cc1 = *reinterpret_cast<const float4*>(&g_c_buf[base1]);
    float4 cv, hv;
    ushort4 hh, hl;
#pragma unroll
    for (int q = 0; q < 4; q++) {
        float iv = sigf((&vi.x)[q] + (&xi.x)[q] + bix[m + q] + bih[m + q]);
        float uv = tanhf((&vu.x)[q] + (&xu.x)[q] + bux[m + q] + buh[m + q]);
        float ov = sigf((&vo.x)[q] + (&xo.x)[q] + boxb[m + q] + boh[m + q]);
        float fx = (&xf.x)[q] + bfx[m + q] + bfh[m + q];
        float fa = sigf(fx + (&f0.x)[q]);
        float fb = sigf(fx + (&f1.x)[q]);
        float c = iv * uv + fa * (&cc0.x)[q] + fb * (&cc1.x)[q];
        (&cv.x)[q] = c;
        float h = ov * tanhf(c);
        (&hv.x)[q] = h;
        split2(h, (&hh.x)[q], (&hl.x)[q]);
    }
    *reinterpret_cast<float4*>(&g_c_buf[base]) = cv;
    *reinterpret_cast<ushort4*>(g_hb_hi + base) = hh;
    *reinterpret_cast<ushort4*>(g_hb_lo + base) = hl;
    if (outp)
        *reinterpret_cast<float4*>(&outp[(size_t)row * MDIM + m]) = hv;
}

// ======================= launch =======================
extern "C" void kernel_launch(void* const* d_in, const int* in_sizes, int n_in,
                              void* d_out, int out_size)
{
    const float* wte = nullptr;
    const float* rel = nullptr;
    const float* Wx[4];  int nWx = 0;   // ix, fx, ux, ox
    const float* Wh[4];  int nWh = 0;   // ih, fh, uh, oh
    const float* b256[8]; int nb = 0;
    const float* Wsih = nullptr;
    const float* Wshh = nullptr;
    const float* bseq[2]; int nbs = 0;

    for (int i = 0; i < n_in; i++) {
        int s = in_sizes[i];
        const float* p = (const float*)d_in[i];
        switch (s) {
            case 33488896: wte = p; break;
            case 4186112:  rel = p; break;
            case 131072:   if (nWx < 4) Wx[nWx++] = p; break;
            case 65536:    if (nWh < 4) Wh[nWh++] = p; break;
            case 256:      if (nb < 8) b256[nb++] = p; break;
            case 327680:   Wsih = p; break;
            case 262144:   Wshh = p; break;
            case 1024:     if (nbs < 2) bseq[nbs++] = p; break;
            default: break;
        }
    }
    const float *Wix = Wx[0], *Wfx = Wx[1], *Wux = Wx[2], *Wox = Wx[3];
    const float *Wih = Wh[0], *Wfh = Wh[1], *Wuh = Wh[2], *Woh = Wh[3];
    const float *bix = b256[0], *bfx = b256[1], *bux = b256[2], *boxb = b256[3];
    const float *bih = b256[4], *bfh = b256[5], *buh = b256[6], *boh = b256[7];
    float* out = (float*)d_out;

    const int SMSZ = 2 * STG;   // 221184 B
    cudaFuncSetAttribute(k_mma<0, 4, 768, 256>,  cudaFuncAttributeMaxDynamicSharedMemorySize, SMSZ);
    cudaFuncSetAttribute(k_mma<1, 8, 1024, 512>, cudaFuncAttributeMaxDynamicSharedMemorySize, SMSZ);
    cudaFuncSetAttribute(k_mma<2, 4, 768, 256>,  cudaFuncAttributeMaxDynamicSharedMemorySize, SMSZ);
    cudaFuncSetAttribute(k_mma<3, 4, 256, 256>,  cudaFuncAttributeMaxDynamicSharedMemorySize, SMSZ);
    cudaFuncSetAttribute(k_mma<5, 8, 1024, 512>, cudaFuncAttributeMaxDynamicSharedMemorySize, SMSZ);
    cudaFuncSetAttribute(k_mma<6, 1, 1024, 64>,  cudaFuncAttributeMaxDynamicSharedMemorySize, SMSZ);

    // conversions
    k_conv_wte<<<32704, 256>>>(wte);
    k_conv_rel<<<4088, 256>>>(rel);
    k_conv_wg<<<2048, 256>>>(Wix, Wux, Wox, Wfx);
    k_conv_wsr<<<256, 256>>>(Wsih);
    k_conv_wc1<<<768, 256>>>(Wsih);
    k_conv_wc2<<<2048, 256>>>(Wsih, Wshh);
    k_conv_wgh<<<768, 256>>>(Wih, Wuh, Woh);
    k_conv_wfh<<<256, 256>>>(Wfh);

    // big projections (full occupancy)
    k_mma<5, 8, 1024, 512><<<dim3(511, 4), 256, SMSZ>>>(0, 0);   // x-proj
    k_mma<6, 1, 1024, 64><<<dim3(511, 4), 256, SMSZ>>>(0, 0);    // rel-proj

    // leaf
    k_comb_leaf<<<8192, 256>>>(bix, bih, bux, buh, boxb, boh);

    // levels 7..0
    for (int L = 7; L >= 0; --L) {
        int P = 1 << L;
        int nodeBase = P - 1;
        k_mma<0, 4, 768, 256><<<dim3(P, 3), 256, SMSZ>>>(nodeBase, P);
        k_comb_c1<<<P * 32, 256>>>(bseq[0], bseq[1], nodeBase);
        k_mma<1, 8, 1024, 512><<<dim3(P, 4), 256, SMSZ>>>(nodeBase, P);
        k_comb_c2<<<P * 32, 256>>>(bseq[0], bseq[1], nodeBase);
        k_mma<2, 4, 768, 256><<<dim3(P, 3), 256, SMSZ>>>(nodeBase, P);
        k_mma<3, 4, 256, 256><<<dim3(2 * P, 1), 256, SMSZ>>>(nodeBase, P);
        k_comb_fin<<<P * 32, 256>>>(bix, bih, bux, buh, boxb, boh, bfx, bfh,
                                    nodeBase, P, (L == 0) ? out : nullptr);
    }
}

// round 16
// speedup vs baseline: 1.3204x; 1.3204x over previous
#include <cuda_runtime.h>
#include <cuda_bf16.h>
#include <cstdint>
#include <cstddef>
#include <math.h>

// Problem constants (B=128, N=511, M=256, R=64, IN=512)
#define BATCH  128
#define NNODES 511
#define MDIM   256
#define RDIM   64
#define INDIM  512

// ---------------- persistent device scratch (no allocation) ----------------
__device__ __align__(16) float g_c_buf[(size_t)NNODES * BATCH * MDIM];
__device__ __align__(16) float g_c1[(size_t)128 * BATCH * MDIM];

// bf16 split activations
__device__ __align__(16) __nv_bfloat16 g_wte_hi[(size_t)BATCH * NNODES * INDIM];
__device__ __align__(16) __nv_bfloat16 g_wte_lo[(size_t)BATCH * NNODES * INDIM];
__device__ __align__(16) __nv_bfloat16 g_relb_hi[(size_t)BATCH * NNODES * RDIM];
__device__ __align__(16) __nv_bfloat16 g_relb_lo[(size_t)BATCH * NNODES * RDIM];
__device__ __align__(16) __nv_bfloat16 g_hb_hi[(size_t)NNODES * BATCH * MDIM];
__device__ __align__(16) __nv_bfloat16 g_hb_lo[(size_t)NNODES * BATCH * MDIM];
__device__ __align__(16) __nv_bfloat16 g_h1b_hi[(size_t)128 * BATCH * MDIM];
__device__ __align__(16) __nv_bfloat16 g_h1b_lo[(size_t)128 * BATCH * MDIM];
__device__ __align__(16) __nv_bfloat16 g_htb_hi[(size_t)128 * BATCH * MDIM];
__device__ __align__(16) __nv_bfloat16 g_htb_lo[(size_t)128 * BATCH * MDIM];

// bf16 split weights (transposed [N][K])
__device__ __align__(16) __nv_bfloat16 g_wg_hi[1024 * 512];    // x-proj: i,u,o,fx
__device__ __align__(16) __nv_bfloat16 g_wg_lo[1024 * 512];
__device__ __align__(16) __nv_bfloat16 g_wsr_hi[1024 * 64];    // rel-proj: seq i,f,g,o
__device__ __align__(16) __nv_bfloat16 g_wsr_lo[1024 * 64];
__device__ __align__(16) __nv_bfloat16 g_wc1_hi[768 * 256];    // cell1 h: i,g,o
__device__ __align__(16) __nv_bfloat16 g_wc1_lo[768 * 256];
__device__ __align__(16) __nv_bfloat16 g_wc2_hi[1024 * 512];   // cell2 h,h1: i,f,g,o
__device__ __align__(16) __nv_bfloat16 g_wc2_lo[1024 * 512];
__device__ __align__(16) __nv_bfloat16 g_wgh_hi[768 * 256];    // gates h: i,u,o
__device__ __align__(16) __nv_bfloat16 g_wgh_lo[768 * 256];
__device__ __align__(16) __nv_bfloat16 g_wfh_hi[256 * 256];
__device__ __align__(16) __nv_bfloat16 g_wfh_lo[256 * 256];

// projection / pre-activation scratch
__device__ __align__(16) float g_xproj[(size_t)65408 * 1024];   // row = b*511+node
__device__ __align__(16) float g_relproj[(size_t)65408 * 1024];
__device__ __align__(16) float g_pre1[(size_t)16384 * 768];
__device__ __align__(16) float g_pre2[(size_t)16384 * 1024];
__device__ __align__(16) float g_preg[(size_t)16384 * 768];
__device__ __align__(16) float g_pref[(size_t)32768 * 256];

__device__ __forceinline__ float sigf(float x) { return 1.0f / (1.0f + expf(-x)); }

__device__ __forceinline__ void split2(float x, unsigned short& h, unsigned short& l) {
    __nv_bfloat16 bh = __float2bfloat16(x);
    h = __bfloat16_as_ushort(bh);
    l = __bfloat16_as_ushort(__float2bfloat16(x - __bfloat162float(bh)));
}

// ---- mma.sync helpers ----
__device__ __forceinline__ uint32_t smem_u32(const void* p) {
    uint32_t a;
    asm("{ .reg .u64 t; cvta.to.shared.u64 t, %1; cvt.u32.u64 %0, t; }" : "=r"(a) : "l"(p));
    return a;
}
__device__ __forceinline__ void ldm4(uint32_t* r, uint32_t addr) {
    asm volatile("ldmatrix.sync.aligned.m8n8.x4.shared.b16 {%0,%1,%2,%3}, [%4];"
        : "=r"(r[0]), "=r"(r[1]), "=r"(r[2]), "=r"(r[3]) : "r"(addr));
}
__device__ __forceinline__ void mma_bf16(float* c, const uint32_t* a,
                                         uint32_t b0, uint32_t b1) {
    asm volatile(
        "mma.sync.aligned.m16n8k16.row.col.f32.bf16.bf16.f32 "
        "{%0,%1,%2,%3}, {%4,%5,%6,%7}, {%8,%9}, {%0,%1,%2,%3};"
        : "+f"(c[0]), "+f"(c[1]), "+f"(c[2]), "+f"(c[3])
        : "r"(a[0]), "r"(a[1]), "r"(a[2]), "r"(a[3]), "r"(b0), "r"(b1));
}
#define CPA16(s, g) asm volatile("cp.async.cg.shared.global [%0], [%1], 16;" :: "r"(s), "l"(g))
#define CPC() asm volatile("cp.async.commit_group;" ::: "memory")
#define CPW(n) asm volatile("cp.async.wait_group %0;" :: "n"(n) : "memory")

// ======================= conversion kernels =======================
__global__ void __launch_bounds__(256)
k_conv_wte(const float* __restrict__ src)
{
    size_t i = ((size_t)blockIdx.x * 256 + threadIdx.x) * 4;
    float4 v = *reinterpret_cast<const float4*>(src + i);
    ushort4 H, L;
#pragma unroll
    for (int q = 0; q < 4; q++) split2((&v.x)[q], (&H.x)[q], (&L.x)[q]);
    *reinterpret_cast<ushort4*>(g_wte_hi + i) = H;
    *reinterpret_cast<ushort4*>(g_wte_lo + i) = L;
}

__global__ void __launch_bounds__(256)
k_conv_rel(const float* __restrict__ src)
{
    size_t i = ((size_t)blockIdx.x * 256 + threadIdx.x) * 4;
    float4 v = *reinterpret_cast<const float4*>(src + i);
    ushort4 H, L;
#pragma unroll
    for (int q = 0; q < 4; q++) split2((&v.x)[q], (&H.x)[q], (&L.x)[q]);
    *reinterpret_cast<ushort4*>(g_relb_hi + i) = H;
    *reinterpret_cast<ushort4*>(g_relb_lo + i) = L;
}

__global__ void __launch_bounds__(256)
k_conv_wg(const float* __restrict__ Wix, const float* __restrict__ Wux,
          const float* __restrict__ Wox, const float* __restrict__ Wfx)
{
    int idx = blockIdx.x * 256 + threadIdx.x;     // [1024][512]
    int n = idx >> 9, k = idx & 511;
    int m = n & 255, gate = n >> 8;
    const float* W = (gate == 0) ? Wix : (gate == 1) ? Wux : (gate == 2) ? Wox : Wfx;
    float x = W[(size_t)k * 256 + m];
    unsigned short h, l;
    split2(x, h, l);
    g_wg_hi[idx] = __ushort_as_bfloat16(h);
    g_wg_lo[idx] = __ushort_as_bfloat16(l);
}

__global__ void __launch_bounds__(256)
k_conv_wsr(const float* __restrict__ Wsih)
{
    int idx = blockIdx.x * 256 + threadIdx.x;     // [1024][64]
    int n = idx >> 6, k = idx & 63;
    float x = Wsih[(size_t)(256 + k) * 1024 + n];
    unsigned short h, l;
    split2(x, h, l);
    g_wsr_hi[idx] = __ushort_as_bfloat16(h);
    g_wsr_lo[idx] = __ushort_as_bfloat16(l);
}

__global__ void __launch_bounds__(256)
k_conv_wc1(const float* __restrict__ Wsih)
{
    int idx = blockIdx.x * 256 + threadIdx.x;     // [768][256]: i,g,o
    int n = idx >> 8, k = idx & 255;
    int m = n & 255, gsel = n >> 8;
    int cbase = (gsel == 0) ? 0 : (gsel == 1 ? 512 : 768);
    float x = Wsih[(size_t)k * 1024 + cbase + m];
    unsigned short h, l;
    split2(x, h, l);
    g_wc1_hi[idx] = __ushort_as_bfloat16(h);
    g_wc1_lo[idx] = __ushort_as_bfloat16(l);
}

__global__ void __launch_bounds__(256)
k_conv_wc2(const float* __restrict__ Wsih, const float* __restrict__ Wshh)
{
    int idx = blockIdx.x * 256 + threadIdx.x;     // [1024][512]: i,f,g,o ; K = h(256)+h1(256)
    int n = idx >> 9, k = idx & 511;
    int m = n & 255, cbase = (n >> 8) * 256;
    float x = (k < 256) ? Wsih[(size_t)k * 1024 + cbase + m]
                        : Wshh[(size_t)(k - 256) * 1024 + cbase + m];
    unsigned short h, l;
    split2(x, h, l);
    g_wc2_hi[idx] = __ushort_as_bfloat16(h);
    g_wc2_lo[idx] = __ushort_as_bfloat16(l);
}

__global__ void __launch_bounds__(256)
k_conv_wgh(const float* __restrict__ Wih, const float* __restrict__ Wuh,
           const float* __restrict__ Woh)
{
    int idx = blockIdx.x * 256 + threadIdx.x;     // [768][256]: i,u,o
    int n = idx >> 8, k = idx & 255;
    int m = n & 255, gate = n >> 8;
    const float* W = (gate == 0) ? Wih : (gate == 1) ? Wuh : Woh;
    float x = W[(size_t)k * 256 + m];
    unsigned short h, l;
    split2(x, h, l);
    g_wgh_hi[idx] = __ushort_as_bfloat16(h);
    g_wgh_lo[idx] = __ushort_as_bfloat16(l);
}

__global__ void __launch_bounds__(256)
k_conv_wfh(const float* __restrict__ Wfh)
{
    int idx = blockIdx.x * 256 + threadIdx.x;     // [256][256]
    int n = idx >> 8, k = idx & 255;
    float x = Wfh[(size_t)k * 256 + n];
    unsigned short h, l;
    split2(x, h, l);
    g_wfh_hi[idx] = __ushort_as_bfloat16(h);
    g_wfh_lo[idx] = __ushort_as_bfloat16(l);
}

// ======================= generic bf16-split mma GEMM =======================
// Block 128 rows x 128 cols, 8 warps (m32 x n64). K in 32-chunks, 2-stage cp.async.
// Stage: Ah@0 (128 rows x 80B), Al@10240, Bh@20480, Bl@30720 -> 40960 B/stage.
// 2 stages = 80 KB -> 2 blocks/SM.
// MODE: 0=cell1(h,K256) 1=cell2(h|h1,K512) 2=gates-h(K256) 3=f(K256)
//       5=bigX(wte,K512) 6=bigR(rel,K64)
#define LPITCH 80
#define STG 40960

template<int MODE, int NC, int COLS, int KTOT>
__global__ void __launch_bounds__(256, 2)
k_mma(int nodeBase, int P)
{
    extern __shared__ char sm[];
    const int tid = threadIdx.x;
    const int rt = blockIdx.x, ny = blockIdx.y;
    const int lane = tid & 31, wid = tid >> 5;
    const int wm = (wid & 3) * 32, wn = (wid >> 2) * 64;
    const int r = tid >> 1, half = tid & 1;

    const __nv_bfloat16* WH;
    const __nv_bfloat16* WL;
    float* pre;
    if (MODE == 0)      { WH = g_wc1_hi; WL = g_wc1_lo; pre = g_pre1; }
    else if (MODE == 1) { WH = g_wc2_hi; WL = g_wc2_lo; pre = g_pre2; }
    else if (MODE == 2) { WH = g_wgh_hi; WL = g_wgh_lo; pre = g_preg; }
    else if (MODE == 3) { WH = g_wfh_hi; WL = g_wfh_lo; pre = g_pref; }
    else if (MODE == 5) { WH = g_wg_hi;  WL = g_wg_lo;  pre = g_xproj; }
    else                { WH = g_wsr_hi; WL = g_wsr_lo; pre = g_relproj; }

    const __nv_bfloat16 *pA0h = nullptr, *pA0l = nullptr;
    const __nv_bfloat16 *pA2h = nullptr, *pA2l = nullptr;
    if (MODE == 5) {
        size_t R = (size_t)rt * 128 + r;
        pA0h = g_wte_hi + R * 512;
        pA0l = g_wte_lo + R * 512;
    } else if (MODE == 6) {
        size_t R = (size_t)rt * 128 + r;
        pA0h = g_relb_hi + R * 64;
        pA0l = g_relb_lo + R * 64;
    } else if (MODE == 3) {
        int rt2 = (rt < P) ? rt : rt - P;
        int rl = rt2 * 128 + r;
        int node = nodeBase + (rl >> 7);
        int b = rl & 127;
        int ch = (rt < P) ? (2 * node + 1) : (2 * node + 2);
        pA0h = g_hb_hi + ((size_t)ch * BATCH + b) * 256;
        pA0l = g_hb_lo + ((size_t)ch * BATCH + b) * 256;
    } else {
        int rl = rt * 128 + r;
        int node = nodeBase + (rl >> 7);
        int b = rl & 127;
        if (MODE == 0) {
            int ch = 2 * node + 1;
            pA0h = g_hb_hi + ((size_t)ch * BATCH + b) * 256;
            pA0l = g_hb_lo + ((size_t)ch * BATCH + b) * 256;
        } else if (MODE == 1) {
            int ch = 2 * node + 2;
            pA0h = g_hb_hi + ((size_t)ch * BATCH + b) * 256;
            pA0l = g_hb_lo + ((size_t)ch * BATCH + b) * 256;
            pA2h = g_h1b_hi + (size_t)rl * 256;
            pA2l = g_h1b_lo + (size_t)rl * 256;
        } else {   // MODE 2
            pA0h = g_htb_hi + (size_t)rl * 256;
            pA0l = g_htb_lo + (size_t)rl * 256;
        }
    }
    const __nv_bfloat16* pBh = WH + (size_t)(ny * 128 + r) * KTOT;
    const __nv_bfloat16* pBl = WL + (size_t)(ny * 128 + r) * KTOT;

    const uint32_t sbase = smem_u32(sm);

    // stage one K-chunk of 32 elements (64 B payload/row, pitch 80)
    auto stage = [&](int c, int s) {
        const __nv_bfloat16 *ah, *al;
        if (MODE == 1 && c >= 8) { ah = pA2h + (c - 8) * 32; al = pA2l + (c - 8) * 32; }
        else                     { ah = pA0h + c * 32;       al = pA0l + c * 32; }
        const char* gah = reinterpret_cast<const char*>(ah) + half * 32;
        const char* gal = reinterpret_cast<const char*>(al) + half * 32;
        const char* gbh = reinterpret_cast<const char*>(pBh + c * 32) + half * 32;
        const char* gbl = reinterpret_cast<const char*>(pBl + c * 32) + half * 32;
        uint32_t base = sbase + (uint32_t)s * STG + (uint32_t)r * LPITCH + half * 32;
        CPA16(base + 0,         gah);
        CPA16(base + 16,        gah + 16);
        CPA16(base + 10240,     gal);
        CPA16(base + 10240 + 16, gal + 16);
        CPA16(base + 20480,     gbh);
        CPA16(base + 20480 + 16, gbh + 16);
        CPA16(base + 30720,     gbl);
        CPA16(base + 30720 + 16, gbl + 16);
        CPC();
    };

    float cacc[2][8][4];
#pragma unroll
    for (int mt = 0; mt < 2; mt++)
#pragma unroll
        for (int j = 0; j < 8; j++)
#pragma unroll
            for (int q = 0; q < 4; q++) cacc[mt][j][q] = 0.0f;

    stage(0, 0);
    for (int c = 0; c < NC; c++) {
        if (c + 1 < NC) { stage(c + 1, (c + 1) & 1); CPW(1); }
        else            { CPW(0); }
        __syncthreads();
        const uint32_t sb = sbase + (uint32_t)(c & 1) * STG;
        const uint32_t aH = sb + 0     + (uint32_t)(wm + (lane & 15)) * LPITCH + (lane >> 4) * 16;
        const uint32_t aL = sb + 10240 + (uint32_t)(wm + (lane & 15)) * LPITCH + (lane >> 4) * 16;
        const uint32_t bH = sb + 20480 + (uint32_t)(wn + (lane & 15)) * LPITCH + (lane >> 4) * 16;
        const uint32_t bL = sb + 30720 + (uint32_t)(wn + (lane & 15)) * LPITCH + (lane >> 4) * 16;
#pragma unroll
        for (int ks = 0; ks < 2; ks++) {
            const uint32_t kb = ks * 32;
            uint32_t bh[8][2], bl[8][2];
#pragma unroll
            for (int p = 0; p < 4; p++) {
                uint32_t t[4];
                ldm4(t, bH + (uint32_t)p * 16 * LPITCH + kb);
                bh[p * 2][0] = t[0]; bh[p * 2][1] = t[2];
                bh[p * 2 + 1][0] = t[1]; bh[p * 2 + 1][1] = t[3];
                ldm4(t, bL + (uint32_t)p * 16 * LPITCH + kb);
                bl[p * 2][0] = t[0]; bl[p * 2][1] = t[2];
                bl[p * 2 + 1][0] = t[1]; bl[p * 2 + 1][1] = t[3];
            }
#pragma unroll
            for (int mt = 0; mt < 2; mt++) {
                uint32_t ah[4], al[4];
                ldm4(ah, aH + (uint32_t)mt * 16 * LPITCH + kb);
                ldm4(al, aL + (uint32_t)mt * 16 * LPITCH + kb);
#pragma unroll
                for (int j = 0; j < 8; j++) {
                    mma_bf16(cacc[mt][j], ah, bh[j][0], bh[j][1]);
                    mma_bf16(cacc[mt][j], ah, bl[j][0], bl[j][1]);
                    mma_bf16(cacc[mt][j], al, bh[j][0], bh[j][1]);
                }
            }
        }
        __syncthreads();
    }

#pragma unroll
    for (int mt = 0; mt < 2; mt++) {
#pragma unroll
        for (int j = 0; j < 8; j++) {
            size_t row = (size_t)rt * 128 + wm + mt * 16 + (lane >> 2);
            int nn = ny * 128 + wn + j * 8 + (lane & 3) * 2;
            float* dst = pre + row * COLS + nn;
            *reinterpret_cast<float2*>(dst) = make_float2(cacc[mt][j][0], cacc[mt][j][1]);
            *reinterpret_cast<float2*>(dst + (size_t)8 * COLS) = make_float2(cacc[mt][j][2], cacc[mt][j][3]);
        }
    }
}

// ======================= combine kernels =======================
__global__ void __launch_bounds__(256)
k_comb_leaf(const float* __restrict__ bix, const float* __restrict__ bih,
            const float* __restrict__ bux, const float* __restrict__ buh,
            const float* __restrict__ boxb, const float* __restrict__ boh)
{
    int idx = blockIdx.x * 256 + threadIdx.x;
    int lin = idx * 4;
    int row = lin >> 8, m = lin & 255;
    int node = 255 + (row >> 7);
    int b = row & 127;
    const float* p = g_xproj + ((size_t)b * NNODES + node) * 1024;
    float4 vi = *reinterpret_cast<const float4*>(p + m);
    float4 vu = *reinterpret_cast<const float4*>(p + 256 + m);
    float4 vo = *reinterpret_cast<const float4*>(p + 512 + m);
    size_t base = ((size_t)node * BATCH + b) * MDIM + m;
    float4 cv;
    ushort4 hh, hl;
#pragma unroll
    for (int q = 0; q < 4; q++) {
        float iv = sigf((&vi.x)[q] + bix[m + q] + bih[m + q]);
        float uv = tanhf((&vu.x)[q] + bux[m + q] + buh[m + q]);
        float ov = sigf((&vo.x)[q] + boxb[m + q] + boh[m + q]);
        float c = iv * uv;
        (&cv.x)[q] = c;
        split2(ov * tanhf(c), (&hh.x)[q], (&hl.x)[q]);
    }
    *reinterpret_cast<float4*>(&g_c_buf[base]) = cv;
    *reinterpret_cast<ushort4*>(g_hb_hi + base) = hh;
    *reinterpret_cast<ushort4*>(g_hb_lo + base) = hl;
}

__global__ void __launch_bounds__(256)
k_comb_c1(const float* __restrict__ bsi, const float* __restrict__ bsh, int nodeBase)
{
    int idx = blockIdx.x * 256 + threadIdx.x;
    int lin = idx * 4;
    int row = lin >> 8, m = lin & 255;
    int node = nodeBase + (row >> 7);
    int b = row & 127;
    int ch = 2 * node + 1;
    const float* p = g_pre1 + (size_t)row * 768;
    const float* rp = g_relproj + ((size_t)b * NNODES + ch) * 1024;
    float4 vi = *reinterpret_cast<const float4*>(p + m);
    float4 vg = *reinterpret_cast<const float4*>(p + 256 + m);
    float4 vo = *reinterpret_cast<const float4*>(p + 512 + m);
    float4 ri = *reinterpret_cast<const float4*>(rp + m);
    float4 rg = *reinterpret_cast<const float4*>(rp + 512 + m);
    float4 ro = *reinterpret_cast<const float4*>(rp + 768 + m);
    size_t base = (size_t)row * MDIM + m;
    float4 cv;
    ushort4 hh, hl;
#pragma unroll
    for (int q = 0; q < 4; q++) {
        float iv = sigf((&vi.x)[q] + (&ri.x)[q] + bsi[m + q] + bsh[m + q]);
        float gv = tanhf((&vg.x)[q] + (&rg.x)[q] + bsi[512 + m + q] + bsh[512 + m + q]);
        float ov = sigf((&vo.x)[q] + (&ro.x)[q] + bsi[768 + m + q] + bsh[768 + m + q]);
        float c1 = iv * gv;
        (&cv.x)[q] = c1;
        split2(ov * tanhf(c1), (&hh.x)[q], (&hl.x)[q]);
    }
    *reinterpret_cast<float4*>(&g_c1[base]) = cv;
    *reinterpret_cast<ushort4*>(g_h1b_hi + base) = hh;
    *reinterpret_cast<ushort4*>(g_h1b_lo + base) = hl;
}

__global__ void __launch_bounds__(256)
k_comb_c2(const float* __restrict__ bsi, const float* __restrict__ bsh, int nodeBase)
{
    int idx = blockIdx.x * 256 + threadIdx.x;
    int lin = idx * 4;
    int row = lin >> 8, m = lin & 255;
    int node = nodeBase + (row >> 7);
    int b = row & 127;
    int ch = 2 * node + 2;
    const float* p = g_pre2 + (size_t)row * 1024;
    const float* rp = g_relproj + ((size_t)b * NNODES + ch) * 1024;
    float4 vi = *reinterpret_cast<const float4*>(p + m);
    float4 vf = *reinterpret_cast<const float4*>(p + 256 + m);
    float4 vg = *reinterpret_cast<const float4*>(p + 512 + m);
    float4 vo = *reinterpret_cast<const float4*>(p + 768 + m);
    float4 ri = *reinterpret_cast<const float4*>(rp + m);
    float4 rf = *reinterpret_cast<const float4*>(rp + 256 + m);
    float4 rg = *reinterpret_cast<const float4*>(rp + 512 + m);
    float4 ro = *reinterpret_cast<const float4*>(rp + 768 + m);
    size_t base = (size_t)row * MDIM + m;
    float4 c1v = *reinterpret_cast<const float4*>(&g_c1[base]);
    ushort4 hh, hl;
#pragma unroll
    for (int q = 0; q < 4; q++) {
        float iv = sigf((&vi.x)[q] + (&ri.x)[q] + bsi[m + q] + bsh[m + q]);
        float fv = sigf((&vf.x)[q] + (&rf.x)[q] + bsi[256 + m + q] + bsh[256 + m + q]);
        float gv = tanhf((&vg.x)[q] + (&rg.x)[q] + bsi[512 + m + q] + bsh[512 + m + q]);
        float ov = sigf((&vo.x)[q] + (&ro.x)[q] + bsi[768 + m + q] + bsh[768 + m + q]);
        float c2 = fv * (&c1v.x)[q] + iv * gv;
        split2(ov * tanhf(c2), (&hh.x)[q], (&hl.x)[q]);
    }
    *reinterpret_cast<ushort4*>(g_htb_hi + base) = hh;
    *reinterpret_cast<ushort4*>(g_htb_lo + base) = hl;
}

__global__ void __launch_bounds__(256)
k_comb_fin(const float* __restrict__ bix, const float* __restrict__ bih,
           const float* __restrict__ bux, const float* __restrict__ buh,
           const float* __restrict__ boxb, const float* __restrict__ boh,
           const float* __restrict__ bfx, const float* __restrict__ bfh,
           int nodeBase, int P, float* __restrict__ outp)
{
    int idx = blockIdx.x * 256 + threadIdx.x;
    int lin = idx * 4;
    int row = lin >> 8, m = lin & 255;
    int node = nodeBase + (row >> 7);
    int b = row & 127;
    const float* p = g_preg + (size_t)row * 768;
    const float* xp = g_xproj + ((size_t)b * NNODES + node) * 1024;
    float4 vi = *reinterpret_cast<const float4*>(p + m);
    float4 vu = *reinterpret_cast<const float4*>(p + 256 + m);
    float4 vo = *reinterpret_cast<const float4*>(p + 512 + m);
    float4 xi = *reinterpret_cast<const float4*>(xp + m);
    float4 xu = *reinterpret_cast<const float4*>(xp + 256 + m);
    float4 xo = *reinterpret_cast<const float4*>(xp + 512 + m);
    float4 xf = *reinterpret_cast<const float4*>(xp + 768 + m);
    float4 f0 = *reinterpret_cast<const float4*>(g_pref + (size_t)row * 256 + m);
    float4 f1 = *reinterpret_cast<const float4*>(g_pref + ((size_t)P * 128 + row) * 256 + m);
    size_t base  = ((size_t)node * BATCH + b) * MDIM + m;
    size_t base0 = ((size_t)(2 * node + 1) * BATCH + b) * MDIM + m;
    size_t base1 = ((size_t)(2 * node + 2) * BATCH + b) * MDIM + m;
    float4 cc0 = *reinterpret_cast<const float4*>(&g_c_buf[base0]);
    float4 cc1 = *reinterpret_cast<const float4*>(&g_c_buf[base1]);
    float4 cv, hv;
    ushort4 hh, hl;
#pragma unroll
    for (int q = 0; q < 4; q++) {
        float iv = sigf((&vi.x)[q] + (&xi.x)[q] + bix[m + q] + bih[m + q]);
        float uv = tanhf((&vu.x)[q] + (&xu.x)[q] + bux[m + q] + buh[m + q]);
        float ov = sigf((&vo.x)[q] + (&xo.x)[q] + boxb[m + q] + boh[m + q]);
        float fx = (&xf.x)[q] + bfx[m + q] + bfh[m + q];
        float fa = sigf(fx + (&f0.x)[q]);
        float fb = sigf(fx + (&f1.x)[q]);
        float c = iv * uv + fa * (&cc0.x)[q] + fb * (&cc1.x)[q];
        (&cv.x)[q] = c;
        float h = ov * tanhf(c);
        (&hv.x)[q] = h;
        split2(h, (&hh.x)[q], (&hl.x)[q]);
    }
    *reinterpret_cast<float4*>(&g_c_buf[base]) = cv;
    *reinterpret_cast<ushort4*>(g_hb_hi + base) = hh;
    *reinterpret_cast<ushort4*>(g_hb_lo + base) = hl;
    if (outp)
        *reinterpret_cast<float4*>(&outp[(size_t)row * MDIM + m]) = hv;
}

// ======================= launch =======================
extern "C" void kernel_launch(void* const* d_in, const int* in_sizes, int n_in,
                              void* d_out, int out_size)
{
    const float* wte = nullptr;
    const float* rel = nullptr;
    const float* Wx[4];  int nWx = 0;   // ix, fx, ux, ox
    const float* Wh[4];  int nWh = 0;   // ih, fh, uh, oh
    const float* b256[8]; int nb = 0;
    const float* Wsih = nullptr;
    const float* Wshh = nullptr;
    const float* bseq[2]; int nbs = 0;

    for (int i = 0; i < n_in; i++) {
        int s = in_sizes[i];
        const float* p = (const float*)d_in[i];
        switch (s) {
            case 33488896: wte = p; break;
            case 4186112:  rel = p; break;
            case 131072:   if (nWx < 4) Wx[nWx++] = p; break;
            case 65536:    if (nWh < 4) Wh[nWh++] = p; break;
            case 256:      if (nb < 8) b256[nb++] = p; break;
            case 327680:   Wsih = p; break;
            case 262144:   Wshh = p; break;
            case 1024:     if (nbs < 2) bseq[nbs++] = p; break;
            default: break;
        }
    }
    const float *Wix = Wx[0], *Wfx = Wx[1], *Wux = Wx[2], *Wox = Wx[3];
    const float *Wih = Wh[0], *Wfh = Wh[1], *Wuh = Wh[2], *Woh = Wh[3];
    const float *bix = b256[0], *bfx = b256[1], *bux = b256[2], *boxb = b256[3];
    const float *bih = b256[4], *bfh = b256[5], *buh = b256[6], *boh = b256[7];
    float* out = (float*)d_out;

    const int SMSZ = 2 * STG;   // 81920 B -> 2 blocks/SM
    cudaFuncSetAttribute(k_mma<0, 8, 768, 256>,   cudaFuncAttributeMaxDynamicSharedMemorySize, SMSZ);
    cudaFuncSetAttribute(k_mma<1, 16, 1024, 512>, cudaFuncAttributeMaxDynamicSharedMemorySize, SMSZ);
    cudaFuncSetAttribute(k_mma<2, 8, 768, 256>,   cudaFuncAttributeMaxDynamicSharedMemorySize, SMSZ);
    cudaFuncSetAttribute(k_mma<3, 8, 256, 256>,   cudaFuncAttributeMaxDynamicSharedMemorySize, SMSZ);
    cudaFuncSetAttribute(k_mma<5, 16, 1024, 512>, cudaFuncAttributeMaxDynamicSharedMemorySize, SMSZ);
    cudaFuncSetAttribute(k_mma<6, 2, 1024, 64>,   cudaFuncAttributeMaxDynamicSharedMemorySize, SMSZ);

    // conversions
    k_conv_wte<<<32704, 256>>>(wte);
    k_conv_rel<<<4088, 256>>>(rel);
    k_conv_wg<<<2048, 256>>>(Wix, Wux, Wox, Wfx);
    k_conv_wsr<<<256, 256>>>(Wsih);
    k_conv_wc1<<<768, 256>>>(Wsih);
    k_conv_wc2<<<2048, 256>>>(Wsih, Wshh);
    k_conv_wgh<<<768, 256>>>(Wih, Wuh, Woh);
    k_conv_wfh<<<256, 256>>>(Wfh);

    // big projections (full occupancy)
    k_mma<5, 16, 1024, 512><<<dim3(511, 8), 256, SMSZ>>>(0, 0);   // x-proj
    k_mma<6, 2, 1024, 64><<<dim3(511, 8), 256, SMSZ>>>(0, 0);     // rel-proj

    // leaf
    k_comb_leaf<<<8192, 256>>>(bix, bih, bux, buh, boxb, boh);

    // levels 7..0
    for (int L = 7; L >= 0; --L) {
        int P = 1 << L;
        int nodeBase = P - 1;
        k_mma<0, 8, 768, 256><<<dim3(P, 6), 256, SMSZ>>>(nodeBase, P);
        k_comb_c1<<<P * 32, 256>>>(bseq[0], bseq[1], nodeBase);
        k_mma<1, 16, 1024, 512><<<dim3(P, 8), 256, SMSZ>>>(nodeBase, P);
        k_comb_c2<<<P * 32, 256>>>(bseq[0], bseq[1], nodeBase);
        k_mma<2, 8, 768, 256><<<dim3(P, 6), 256, SMSZ>>>(nodeBase, P);
        k_mma<3, 8, 256, 256><<<dim3(2 * P, 2), 256, SMSZ>>>(nodeBase, P);
        k_comb_fin<<<P * 32, 256>>>(bix, bih, bux, buh, boxb, boh, bfx, bfh,
                                    nodeBase, P, (L == 0) ? out : nullptr);
    }
}